// round 10
// baseline (speedup 1.0000x reference)
#include <cuda_runtime.h>
#include <cuda_fp16.h>
#include <cstdint>

// Problem dims
#define M_TOTAL 16384      // 8 * 2048
#define N_TOTAL 4096       // OUT_FEATURES
#define K_TOTAL 4096       // IN_FEATURES

// GEMM tiling: 256x128 CTA tile, BK=64, 4-stage, warp-specialized producer
#define BM 256
#define BN 128
#define BK 64
#define STAGES 4
#define KT (K_TOTAL / BK)        // 64
#define PITCH 144                 // 128B data + 16B pad per row (conflict-free ldsm)

#define A_STAGE_B (BM * PITCH)              // 36864
#define B_STAGE_B (BN * PITCH)              // 18432
#define STAGE_B   (A_STAGE_B + B_STAGE_B)   // 55296
#define MBAR_OFF  (STAGES * STAGE_B)        // 221184
#define MBAR_FULL(s)  (MBAR_OFF + (s) * 8)
#define MBAR_EMPTY(s) (MBAR_OFF + 32 + (s) * 8)
#define SMEM_TOTAL (MBAR_OFF + 64)          // 221248 -> 1 CTA/SM

// Static scratch: fp16 copies of x and dequantized W
__device__ __half g_Xh[(size_t)M_TOTAL * K_TOTAL];   // 128 MB
__device__ __half g_Wh[(size_t)N_TOTAL * K_TOTAL];   // 32 MB

__constant__ float c_nf4[16] = {
    -1.0f, -0.6961928009986877f, -0.5250730514526367f, -0.39491748809814453f,
    -0.28444138169288635f, -0.18477343022823334f, -0.09105003625154495f, 0.0f,
    0.07958029955625534f, 0.16093020141124725f, 0.24611230194568634f,
    0.33791524171829224f, 0.44070982933044434f, 0.5626170039176941f,
    0.7229568362236023f, 1.0f};

__device__ __forceinline__ uint32_t smem_u32(const void* p) {
    return (uint32_t)__cvta_generic_to_shared(p);
}
__device__ __forceinline__ void cp_async16(uint32_t dst, const void* src) {
    asm volatile("cp.async.cg.shared.global [%0], [%1], 16;" :: "r"(dst), "l"(src));
}
__device__ __forceinline__ void ldsm_x4(uint32_t* r, uint32_t a) {
    asm volatile("ldmatrix.sync.aligned.m8n8.x4.shared.b16 {%0,%1,%2,%3}, [%4];"
                 : "=r"(r[0]), "=r"(r[1]), "=r"(r[2]), "=r"(r[3]) : "r"(a));
}
__device__ __forceinline__ void mbar_init(uint32_t a, uint32_t cnt) {
    asm volatile("mbarrier.init.shared.b64 [%0], %1;" :: "r"(a), "r"(cnt) : "memory");
}
__device__ __forceinline__ void mbar_arrive(uint32_t a) {
    asm volatile("mbarrier.arrive.shared.b64 _, [%0];" :: "r"(a) : "memory");
}
__device__ __forceinline__ void cp_async_arrive(uint32_t a) {
    asm volatile("cp.async.mbarrier.arrive.noinc.shared.b64 [%0];" :: "r"(a) : "memory");
}
__device__ __forceinline__ void mbar_wait(uint32_t a, uint32_t parity) {
    asm volatile(
        "{\n\t.reg .pred P;\n\t"
        "WL%=:\n\t"
        "mbarrier.try_wait.parity.acquire.cta.shared::cta.b64 P, [%0], %1, 0x989680;\n\t"
        "@!P bra WL%=;\n\t}"
        :: "r"(a), "r"(parity) : "memory");
}

// ---------------------------------------------------------------------------
// Merged prep: x fp32->fp16 AND NF4 dequant of W, one launch.
// ---------------------------------------------------------------------------
#define XB 65536
#define WB 8192
__global__ void prep_kernel(const float* __restrict__ x,
                            const int* __restrict__ wp,
                            const float* __restrict__ scale,
                            __half* __restrict__ xh,
                            __half* __restrict__ wh) {
    if (blockIdx.x < XB) {
        long long i = (long long)blockIdx.x * blockDim.x + threadIdx.x;
        float4 v = *(const float4*)(x + i * 4);
        __half2 h0 = __floats2half2_rn(v.x, v.y);
        __half2 h1 = __floats2half2_rn(v.z, v.w);
        *(__half2*)(xh + i * 4)     = h0;
        *(__half2*)(xh + i * 4 + 2) = h1;
    } else {
        int i = (blockIdx.x - XB) * blockDim.x + threadIdx.x;
        const float s = __ldg(scale);
        int4 v = *(const int4*)(wp + (size_t)i * 4);
        int vv[4] = {v.x, v.y, v.z, v.w};
        __align__(16) __half h[8];
#pragma unroll
        for (int j = 0; j < 4; j++) {
            h[2 * j]     = __float2half(c_nf4[vv[j] & 15] * s);
            h[2 * j + 1] = __float2half(c_nf4[(vv[j] >> 4) & 15] * s);
        }
        *(uint4*)(wh + (size_t)i * 8) = *(const uint4*)h;
    }
}

// ---------------------------------------------------------------------------
// GEMM: C[M,N] = A[M,K](fp16) * B[N,K]^T(fp16) + bias, fp32 out.
// 256x128 CTA tile. Warps 0-15: consumers (64x32 warp tiles, m16n8k16 fp32-acc).
// Warp 16: cp.async producer. mbarrier full/empty pipeline, NO __syncthreads
// in the mainloop. 544 threads, 1 CTA/SM.
// ---------------------------------------------------------------------------
__global__ void __launch_bounds__(544, 1)
gemm_f16_kernel(const __half* __restrict__ A, const __half* __restrict__ Bm,
                const float* __restrict__ bias, float* __restrict__ C) {
    extern __shared__ __align__(16) char smem[];
    const uint32_t sb = smem_u32(smem);

    const int tid  = threadIdx.x;
    const int lane = tid & 31;
    const int warp = tid >> 5;
    const int bm = blockIdx.y * BM;
    const int bn = blockIdx.x * BN;

    if (tid == 0) {
#pragma unroll
        for (int s = 0; s < STAGES; s++) {
            mbar_init(sb + MBAR_FULL(s), 32);    // 32 producer-lane async arrivals
            mbar_init(sb + MBAR_EMPTY(s), 16);   // 16 consumer warps (1 lane each)
        }
    }
    __syncthreads();

    if (warp == 16) {
        // ================= producer warp =================
        const int r0 = lane >> 3;             // 0..3
        const int cc = (lane & 7) * 8;        // halves: 0..56
        const __half* Ag = A  + (size_t)(bm + r0) * K_TOTAL + cc;
        const __half* Bg = Bm + (size_t)(bn + r0) * K_TOTAL + cc;
        const uint32_t sA = sb + r0 * PITCH + cc * 2;
        const uint32_t sB = sA + A_STAGE_B;

        int s = 0, r = 0;   // stage cursor, round counter
#pragma unroll 1
        for (int kt = 0; kt < KT; kt++) {
            if (kt >= STAGES)
                mbar_wait(sb + MBAR_EMPTY(s), (r - 1) & 1);
            const uint32_t so = (uint32_t)s * STAGE_B;
            const size_t g = (size_t)kt * BK;
            const __half* a = Ag + g;
            const __half* b = Bg + g;
#pragma unroll 8
            for (int j = 0; j < 64; j++)       // A rows r0 + 4j (256 rows)
                cp_async16(sA + so + j * (4 * PITCH), a + (size_t)j * 4 * K_TOTAL);
#pragma unroll 8
            for (int j = 0; j < 32; j++)       // B rows r0 + 4j (128 rows)
                cp_async16(sB + so + j * (4 * PITCH), b + (size_t)j * 4 * K_TOTAL);
            cp_async_arrive(sb + MBAR_FULL(s));
            if (++s == STAGES) { s = 0; r++; }
        }
        return;
    }

    // ================= consumer warps 0..15 =================
    const int wm = (warp >> 2) * 64;   // 0,64,128,192
    const int wn = (warp & 3) * 32;    // 0,32,64,96

    float acc[4][4][4];
#pragma unroll
    for (int i = 0; i < 4; i++)
#pragma unroll
        for (int j = 0; j < 4; j++)
#pragma unroll
            for (int r = 0; r < 4; r++) acc[i][j][r] = 0.f;

    // ldmatrix per-lane bases (stage 0)
    const int arow  = lane & 15;
    const int aoff8 = (lane >> 4) * 8;
    const int brow  = (lane & 7) + ((lane >> 4) & 1) * 8;
    const int boff8 = ((lane >> 3) & 1) * 8;
    const uint32_t a_base = sb + (wm + arow) * PITCH + aoff8 * 2;
    const uint32_t b_base = sb + A_STAGE_B + (wn + brow) * PITCH + boff8 * 2;

    int s = 0, ph = 0;
#pragma unroll 1
    for (int kt = 0; kt < KT; kt++) {
        mbar_wait(sb + MBAR_FULL(s), ph);
        const uint32_t boff = (uint32_t)s * STAGE_B;

#pragma unroll
        for (int ks = 0; ks < 4; ks++) {
            uint32_t ar[4][4], br[4][2];
#pragma unroll
            for (int mi = 0; mi < 4; mi++)
                ldsm_x4(ar[mi], a_base + boff + ks * 32 + mi * (16 * PITCH));
#pragma unroll
            for (int nb = 0; nb < 2; nb++) {
                uint32_t r[4];
                ldsm_x4(r, b_base + boff + ks * 32 + nb * (16 * PITCH));
                br[nb * 2][0] = r[0]; br[nb * 2][1] = r[1];
                br[nb * 2 + 1][0] = r[2]; br[nb * 2 + 1][1] = r[3];
            }
            if (ks == 3 && lane == 0)          // all this warp's LDSM for stage done
                mbar_arrive(sb + MBAR_EMPTY(s));
#pragma unroll
            for (int mi = 0; mi < 4; mi++)
#pragma unroll
                for (int ni = 0; ni < 4; ni++)
                    asm volatile(
                        "mma.sync.aligned.m16n8k16.row.col.f32.f16.f16.f32 "
                        "{%0,%1,%2,%3}, {%4,%5,%6,%7}, {%8,%9}, {%0,%1,%2,%3};"
                        : "+f"(acc[mi][ni][0]), "+f"(acc[mi][ni][1]),
                          "+f"(acc[mi][ni][2]), "+f"(acc[mi][ni][3])
                        : "r"(ar[mi][0]), "r"(ar[mi][1]), "r"(ar[mi][2]), "r"(ar[mi][3]),
                          "r"(br[ni][0]), "r"(br[ni][1]));
        }

        if (++s == STAGES) { s = 0; ph ^= 1; }
    }

    // --- epilogue: bias add + fp32 store
#pragma unroll
    for (int mi = 0; mi < 4; mi++) {
        const int row0 = bm + wm + mi * 16 + (lane >> 2);
#pragma unroll
        for (int ni = 0; ni < 4; ni++) {
            const int col = bn + wn + ni * 8 + (lane & 3) * 2;
            const float b0 = bias[col];
            const float b1 = bias[col + 1];
            float2 v0 = make_float2(acc[mi][ni][0] + b0, acc[mi][ni][1] + b1);
            float2 v1 = make_float2(acc[mi][ni][2] + b0, acc[mi][ni][3] + b1);
            *(float2*)&C[(size_t)row0 * N_TOTAL + col]       = v0;
            *(float2*)&C[(size_t)(row0 + 8) * N_TOTAL + col] = v1;
        }
    }
}

// ---------------------------------------------------------------------------
// Launch
// ---------------------------------------------------------------------------
extern "C" void kernel_launch(void* const* d_in, const int* in_sizes, int n_in,
                              void* d_out, int out_size) {
    const float* x     = (const float*)d_in[0];
    const int*   wp    = (const int*)d_in[1];
    const float* scale = (const float*)d_in[2];
    const float* bias  = (const float*)d_in[3];
    float*       out   = (float*)d_out;

    __half* xh = nullptr;
    __half* wh = nullptr;
    cudaGetSymbolAddress((void**)&xh, g_Xh);
    cudaGetSymbolAddress((void**)&wh, g_Wh);

    prep_kernel<<<XB + WB, 256>>>(x, wp, scale, xh, wh);

    cudaFuncSetAttribute(gemm_f16_kernel,
                         cudaFuncAttributeMaxDynamicSharedMemorySize, SMEM_TOTAL);
    dim3 grid(N_TOTAL / BN, M_TOTAL / BM);   // (32, 64)
    gemm_f16_kernel<<<grid, 544, SMEM_TOTAL>>>(xh, wh, bias, out);
}

// round 11
// speedup vs baseline: 1.0803x; 1.0803x over previous
#include <cuda_runtime.h>
#include <cuda_fp16.h>
#include <cstdint>

// Problem dims
#define M_TOTAL 16384      // 8 * 2048
#define N_TOTAL 4096       // OUT_FEATURES
#define K_TOTAL 4096       // IN_FEATURES

// GEMM tiling: BK=64, 3-stage, warp-specialized producer (R9 base)
#define BM 128
#define BN 128
#define BK 64
#define STAGES 3
#define KT (K_TOTAL / BK)        // 64
#define PITCH 144                 // 128B data + 16B pad per row (conflict-free ldsm)

#define A_STAGE_B (BM * PITCH)              // 18432
#define B_STAGE_B (BN * PITCH)              // 18432
#define STAGE_B   (A_STAGE_B + B_STAGE_B)   // 36864
#define MBAR_OFF  (STAGES * STAGE_B)        // 110592
#define MBAR_FULL(s)  (MBAR_OFF + (s) * 8)
#define MBAR_EMPTY(s) (MBAR_OFF + 24 + (s) * 8)
#define SMEM_TOTAL (MBAR_OFF + 64)          // 110656 -> 2 CTAs/SM

// Static scratch: fp16 copies of x and dequantized W
__device__ __half g_Xh[(size_t)M_TOTAL * K_TOTAL];   // 128 MB
__device__ __half g_Wh[(size_t)N_TOTAL * K_TOTAL];   // 32 MB

__constant__ float c_nf4[16] = {
    -1.0f, -0.6961928009986877f, -0.5250730514526367f, -0.39491748809814453f,
    -0.28444138169288635f, -0.18477343022823334f, -0.09105003625154495f, 0.0f,
    0.07958029955625534f, 0.16093020141124725f, 0.24611230194568634f,
    0.33791524171829224f, 0.44070982933044434f, 0.5626170039176941f,
    0.7229568362236023f, 1.0f};

__device__ __forceinline__ uint32_t smem_u32(const void* p) {
    return (uint32_t)__cvta_generic_to_shared(p);
}
__device__ __forceinline__ void cp_async16(uint32_t dst, const void* src) {
    asm volatile("cp.async.cg.shared.global [%0], [%1], 16;" :: "r"(dst), "l"(src));
}
__device__ __forceinline__ void ldsm_x4(uint32_t* r, uint32_t a) {
    asm volatile("ldmatrix.sync.aligned.m8n8.x4.shared.b16 {%0,%1,%2,%3}, [%4];"
                 : "=r"(r[0]), "=r"(r[1]), "=r"(r[2]), "=r"(r[3]) : "r"(a));
}
__device__ __forceinline__ void mbar_init(uint32_t a, uint32_t cnt) {
    asm volatile("mbarrier.init.shared.b64 [%0], %1;" :: "r"(a), "r"(cnt) : "memory");
}
__device__ __forceinline__ void mbar_arrive(uint32_t a) {
    asm volatile("mbarrier.arrive.shared.b64 _, [%0];" :: "r"(a) : "memory");
}
__device__ __forceinline__ void cp_async_arrive(uint32_t a) {
    asm volatile("cp.async.mbarrier.arrive.noinc.shared.b64 [%0];" :: "r"(a) : "memory");
}
__device__ __forceinline__ void mbar_wait(uint32_t a, uint32_t parity) {
    asm volatile(
        "{\n\t.reg .pred P;\n\t"
        "WL%=:\n\t"
        "mbarrier.try_wait.parity.acquire.cta.shared::cta.b64 P, [%0], %1, 0x989680;\n\t"
        "@!P bra WL%=;\n\t}"
        :: "r"(a), "r"(parity) : "memory");
}

// ---------------------------------------------------------------------------
// Merged prep: x fp32->fp16 AND NF4 dequant of W, one launch.
// ---------------------------------------------------------------------------
#define XB 65536
#define WB 8192
__global__ void prep_kernel(const float* __restrict__ x,
                            const int* __restrict__ wp,
                            const float* __restrict__ scale,
                            __half* __restrict__ xh,
                            __half* __restrict__ wh) {
    if (blockIdx.x < XB) {
        long long i = (long long)blockIdx.x * blockDim.x + threadIdx.x;
        float4 v = *(const float4*)(x + i * 4);
        __half2 h0 = __floats2half2_rn(v.x, v.y);
        __half2 h1 = __floats2half2_rn(v.z, v.w);
        *(__half2*)(xh + i * 4)     = h0;
        *(__half2*)(xh + i * 4 + 2) = h1;
    } else {
        int i = (blockIdx.x - XB) * blockDim.x + threadIdx.x;
        const float s = __ldg(scale);
        int4 v = *(const int4*)(wp + (size_t)i * 4);
        int vv[4] = {v.x, v.y, v.z, v.w};
        __align__(16) __half h[8];
#pragma unroll
        for (int j = 0; j < 4; j++) {
            h[2 * j]     = __float2half(c_nf4[vv[j] & 15] * s);
            h[2 * j + 1] = __float2half(c_nf4[(vv[j] >> 4) & 15] * s);
        }
        *(uint4*)(wh + (size_t)i * 8) = *(const uint4*)h;
    }
}

// ---------------------------------------------------------------------------
// GEMM: C[M,N] = A[M,K](fp16) * B[N,K]^T(fp16) + bias, fp32 out.
// 128x128 CTA tile. Warps 0-7: consumers (64x32 tiles), warp 8: producer.
// mbarrier pipeline, ks phase-staggered per warp-row, B-fragment double buffer.
// 288 threads, 2 CTAs/SM.
// ---------------------------------------------------------------------------
__global__ void __launch_bounds__(288, 2)
gemm_f16_kernel(const __half* __restrict__ A, const __half* __restrict__ Bm,
                const float* __restrict__ bias, float* __restrict__ C) {
    extern __shared__ __align__(16) char smem[];
    const uint32_t sb = smem_u32(smem);

    const int tid  = threadIdx.x;
    const int lane = tid & 31;
    const int warp = tid >> 5;
    const int bm = blockIdx.y * BM;
    const int bn = blockIdx.x * BN;

    if (tid == 0) {
#pragma unroll
        for (int s = 0; s < STAGES; s++) {
            mbar_init(sb + MBAR_FULL(s), 32);   // 32 producer-lane async arrivals
            mbar_init(sb + MBAR_EMPTY(s), 8);   // 8 consumer warps (1 lane each)
        }
    }
    __syncthreads();

    if (warp == 8) {
        // ================= producer warp =================
        const int r0 = lane >> 3;             // 0..3
        const int cc = (lane & 7) * 8;        // halves: 0..56
        const __half* Ag = A  + (size_t)(bm + r0) * K_TOTAL + cc;
        const __half* Bg = Bm + (size_t)(bn + r0) * K_TOTAL + cc;
        const uint32_t sA = sb + r0 * PITCH + cc * 2;
        const uint32_t sB = sA + A_STAGE_B;

        int s = 0, r = 0;
#pragma unroll 1
        for (int kt = 0; kt < KT; kt++) {
            if (kt >= STAGES)
                mbar_wait(sb + MBAR_EMPTY(s), (r - 1) & 1);
            const uint32_t so = (uint32_t)s * STAGE_B;
            const size_t g = (size_t)kt * BK;
            const __half* a = Ag + g;
            const __half* b = Bg + g;
#pragma unroll 8
            for (int j = 0; j < 32; j++)       // A rows r0 + 4j
                cp_async16(sA + so + j * (4 * PITCH), a + (size_t)j * 4 * K_TOTAL);
#pragma unroll 8
            for (int j = 0; j < 32; j++)       // B rows r0 + 4j
                cp_async16(sB + so + j * (4 * PITCH), b + (size_t)j * 4 * K_TOTAL);
            cp_async_arrive(sb + MBAR_FULL(s));
            if (++s == STAGES) { s = 0; r++; }
        }
        return;
    }

    // ================= consumer warps 0..7 =================
    const int wrow = warp >> 2;        // 0 or 1 (warp row)
    const int wm = wrow * 64;
    const int wn = (warp & 3) * 32;    // 0,32,64,96
    const int ksh = wrow * 2;          // ks phase stagger: row1 starts at ks=2

    float acc[4][4][4];
#pragma unroll
    for (int i = 0; i < 4; i++)
#pragma unroll
        for (int j = 0; j < 4; j++)
#pragma unroll
            for (int r = 0; r < 4; r++) acc[i][j][r] = 0.f;

    // ldmatrix per-lane bases (stage 0)
    const int arow  = lane & 15;
    const int aoff8 = (lane >> 4) * 8;
    const int brow  = (lane & 7) + ((lane >> 4) & 1) * 8;
    const int boff8 = ((lane >> 3) & 1) * 8;
    const uint32_t a_base = sb + (wm + arow) * PITCH + aoff8 * 2;
    const uint32_t b_base = sb + A_STAGE_B + (wn + brow) * PITCH + boff8 * 2;

    int s = 0, ph = 0;
#pragma unroll 1
    for (int kt = 0; kt < KT; kt++) {
        mbar_wait(sb + MBAR_FULL(s), ph);
        const uint32_t boff = (uint32_t)s * STAGE_B;

        // prologue of ks-pipeline: load B fragments for first ks slot
        uint32_t br[2][4][2];      // double-buffered B fragments
        {
            const uint32_t k0 = (uint32_t)(ksh & 3) * 32;
#pragma unroll
            for (int nb = 0; nb < 2; nb++) {
                uint32_t r[4];
                ldsm_x4(r, b_base + boff + k0 + nb * (16 * PITCH));
                br[0][nb * 2][0] = r[0]; br[0][nb * 2][1] = r[1];
                br[0][nb * 2 + 1][0] = r[2]; br[0][nb * 2 + 1][1] = r[3];
            }
        }

#pragma unroll
        for (int kk = 0; kk < 4; kk++) {
            const int ks  = (kk + ksh) & 3;
            const int cur = kk & 1;
            const int nxt = cur ^ 1;

            // A fragments for this ks
            uint32_t ar[4][4];
#pragma unroll
            for (int mi = 0; mi < 4; mi++)
                ldsm_x4(ar[mi], a_base + boff + ks * 32 + mi * (16 * PITCH));

            // prefetch B fragments for next ks into the other buffer
            if (kk < 3) {
                const uint32_t kn = (uint32_t)((kk + 1 + ksh) & 3) * 32;
#pragma unroll
                for (int nb = 0; nb < 2; nb++) {
                    uint32_t r[4];
                    ldsm_x4(r, b_base + boff + kn + nb * (16 * PITCH));
                    br[nxt][nb * 2][0] = r[0]; br[nxt][nb * 2][1] = r[1];
                    br[nxt][nb * 2 + 1][0] = r[2]; br[nxt][nb * 2 + 1][1] = r[3];
                }
            }
            if (kk == 3 && lane == 0)     // all this warp's LDSM for stage done
                mbar_arrive(sb + MBAR_EMPTY(s));

#pragma unroll
            for (int mi = 0; mi < 4; mi++)
#pragma unroll
                for (int ni = 0; ni < 4; ni++)
                    asm volatile(
                        "mma.sync.aligned.m16n8k16.row.col.f32.f16.f16.f32 "
                        "{%0,%1,%2,%3}, {%4,%5,%6,%7}, {%8,%9}, {%0,%1,%2,%3};"
                        : "+f"(acc[mi][ni][0]), "+f"(acc[mi][ni][1]),
                          "+f"(acc[mi][ni][2]), "+f"(acc[mi][ni][3])
                        : "r"(ar[mi][0]), "r"(ar[mi][1]), "r"(ar[mi][2]), "r"(ar[mi][3]),
                          "r"(br[cur][ni][0]), "r"(br[cur][ni][1]));
        }

        if (++s == STAGES) { s = 0; ph ^= 1; }
    }

    // --- epilogue: bias add + fp32 store
#pragma unroll
    for (int mi = 0; mi < 4; mi++) {
        const int row0 = bm + wm + mi * 16 + (lane >> 2);
#pragma unroll
        for (int ni = 0; ni < 4; ni++) {
            const int col = bn + wn + ni * 8 + (lane & 3) * 2;
            const float b0 = bias[col];
            const float b1 = bias[col + 1];
            float2 v0 = make_float2(acc[mi][ni][0] + b0, acc[mi][ni][1] + b1);
            float2 v1 = make_float2(acc[mi][ni][2] + b0, acc[mi][ni][3] + b1);
            *(float2*)&C[(size_t)row0 * N_TOTAL + col]       = v0;
            *(float2*)&C[(size_t)(row0 + 8) * N_TOTAL + col] = v1;
        }
    }
}

// ---------------------------------------------------------------------------
// Launch
// ---------------------------------------------------------------------------
extern "C" void kernel_launch(void* const* d_in, const int* in_sizes, int n_in,
                              void* d_out, int out_size) {
    const float* x     = (const float*)d_in[0];
    const int*   wp    = (const int*)d_in[1];
    const float* scale = (const float*)d_in[2];
    const float* bias  = (const float*)d_in[3];
    float*       out   = (float*)d_out;

    __half* xh = nullptr;
    __half* wh = nullptr;
    cudaGetSymbolAddress((void**)&xh, g_Xh);
    cudaGetSymbolAddress((void**)&wh, g_Wh);

    prep_kernel<<<XB + WB, 256>>>(x, wp, scale, xh, wh);

    cudaFuncSetAttribute(gemm_f16_kernel,
                         cudaFuncAttributeMaxDynamicSharedMemorySize, SMEM_TOTAL);
    dim3 grid(N_TOTAL / BN, M_TOTAL / BM);   // (32, 128)
    gemm_f16_kernel<<<grid, 288, SMEM_TOTAL>>>(xh, wh, bias, out);
}

// round 12
// speedup vs baseline: 1.0999x; 1.0181x over previous
#include <cuda_runtime.h>
#include <cuda_fp16.h>
#include <cstdint>

// Problem dims
#define M_TOTAL 16384      // 8 * 2048
#define N_TOTAL 4096       // OUT_FEATURES
#define K_TOTAL 4096       // IN_FEATURES

// GEMM tiling: BK=64, 3-stage, warp-specialized producer, 64x64 warp tiles
#define BM 128
#define BN 128
#define BK 64
#define STAGES 3
#define KT (K_TOTAL / BK)        // 64
#define PITCH 144                 // 128B data + 16B pad per row (conflict-free ldsm)

#define A_STAGE_B (BM * PITCH)              // 18432
#define B_STAGE_B (BN * PITCH)              // 18432
#define STAGE_B   (A_STAGE_B + B_STAGE_B)   // 36864
#define MBAR_OFF  (STAGES * STAGE_B)        // 110592
#define MBAR_FULL(s)  (MBAR_OFF + (s) * 8)
#define MBAR_EMPTY(s) (MBAR_OFF + 24 + (s) * 8)
#define SMEM_TOTAL (MBAR_OFF + 64)          // 110656 -> 2 CTAs/SM

// Static scratch: fp16 copies of x and dequantized W
__device__ __half g_Xh[(size_t)M_TOTAL * K_TOTAL];   // 128 MB
__device__ __half g_Wh[(size_t)N_TOTAL * K_TOTAL];   // 32 MB

__constant__ float c_nf4[16] = {
    -1.0f, -0.6961928009986877f, -0.5250730514526367f, -0.39491748809814453f,
    -0.28444138169288635f, -0.18477343022823334f, -0.09105003625154495f, 0.0f,
    0.07958029955625534f, 0.16093020141124725f, 0.24611230194568634f,
    0.33791524171829224f, 0.44070982933044434f, 0.5626170039176941f,
    0.7229568362236023f, 1.0f};

__device__ __forceinline__ uint32_t smem_u32(const void* p) {
    return (uint32_t)__cvta_generic_to_shared(p);
}
__device__ __forceinline__ void cp_async16(uint32_t dst, const void* src) {
    asm volatile("cp.async.cg.shared.global [%0], [%1], 16;" :: "r"(dst), "l"(src));
}
__device__ __forceinline__ void ldsm_x4(uint32_t* r, uint32_t a) {
    asm volatile("ldmatrix.sync.aligned.m8n8.x4.shared.b16 {%0,%1,%2,%3}, [%4];"
                 : "=r"(r[0]), "=r"(r[1]), "=r"(r[2]), "=r"(r[3]) : "r"(a));
}
__device__ __forceinline__ void mbar_init(uint32_t a, uint32_t cnt) {
    asm volatile("mbarrier.init.shared.b64 [%0], %1;" :: "r"(a), "r"(cnt) : "memory");
}
__device__ __forceinline__ void mbar_arrive(uint32_t a) {
    asm volatile("mbarrier.arrive.shared.b64 _, [%0];" :: "r"(a) : "memory");
}
__device__ __forceinline__ void cp_async_arrive(uint32_t a) {
    asm volatile("cp.async.mbarrier.arrive.noinc.shared.b64 [%0];" :: "r"(a) : "memory");
}
__device__ __forceinline__ void mbar_wait(uint32_t a, uint32_t parity) {
    asm volatile(
        "{\n\t.reg .pred P;\n\t"
        "WL%=:\n\t"
        "mbarrier.try_wait.parity.acquire.cta.shared::cta.b64 P, [%0], %1, 0x989680;\n\t"
        "@!P bra WL%=;\n\t}"
        :: "r"(a), "r"(parity) : "memory");
}

// ---------------------------------------------------------------------------
// Merged prep: x fp32->fp16 AND NF4 dequant of W, one launch.
// ---------------------------------------------------------------------------
#define XB 65536
#define WB 8192
__global__ void prep_kernel(const float* __restrict__ x,
                            const int* __restrict__ wp,
                            const float* __restrict__ scale,
                            __half* __restrict__ xh,
                            __half* __restrict__ wh) {
    if (blockIdx.x < XB) {
        long long i = (long long)blockIdx.x * blockDim.x + threadIdx.x;
        float4 v = *(const float4*)(x + i * 4);
        __half2 h0 = __floats2half2_rn(v.x, v.y);
        __half2 h1 = __floats2half2_rn(v.z, v.w);
        *(__half2*)(xh + i * 4)     = h0;
        *(__half2*)(xh + i * 4 + 2) = h1;
    } else {
        int i = (blockIdx.x - XB) * blockDim.x + threadIdx.x;
        const float s = __ldg(scale);
        int4 v = *(const int4*)(wp + (size_t)i * 4);
        int vv[4] = {v.x, v.y, v.z, v.w};
        __align__(16) __half h[8];
#pragma unroll
        for (int j = 0; j < 4; j++) {
            h[2 * j]     = __float2half(c_nf4[vv[j] & 15] * s);
            h[2 * j + 1] = __float2half(c_nf4[(vv[j] >> 4) & 15] * s);
        }
        *(uint4*)(wh + (size_t)i * 8) = *(const uint4*)h;
    }
}

// ---------------------------------------------------------------------------
// GEMM: C[M,N] = A[M,K](fp16) * B[N,K]^T(fp16) + bias, fp32 out.
// 128x128 CTA tile. Warps 0-3: consumers (64x64 warp tiles, 2x2 grid).
// Warp 4: cp.async producer. mbarrier pipeline, no __syncthreads in mainloop.
// 160 threads, 2 CTAs/SM. Halved LDSM redundancy vs 64x32 tiles.
// ---------------------------------------------------------------------------
__global__ void __launch_bounds__(160, 2)
gemm_f16_kernel(const __half* __restrict__ A, const __half* __restrict__ Bm,
                const float* __restrict__ bias, float* __restrict__ C) {
    extern __shared__ __align__(16) char smem[];
    const uint32_t sb = smem_u32(smem);

    const int tid  = threadIdx.x;
    const int lane = tid & 31;
    const int warp = tid >> 5;
    const int bm = blockIdx.y * BM;
    const int bn = blockIdx.x * BN;

    if (tid == 0) {
#pragma unroll
        for (int s = 0; s < STAGES; s++) {
            mbar_init(sb + MBAR_FULL(s), 32);   // 32 producer-lane async arrivals
            mbar_init(sb + MBAR_EMPTY(s), 4);   // 4 consumer warps (1 lane each)
        }
    }
    __syncthreads();

    if (warp == 4) {
        // ================= producer warp =================
        const int r0 = lane >> 3;             // 0..3
        const int cc = (lane & 7) * 8;        // halves: 0..56
        const __half* Ag = A  + (size_t)(bm + r0) * K_TOTAL + cc;
        const __half* Bg = Bm + (size_t)(bn + r0) * K_TOTAL + cc;
        const uint32_t sA = sb + r0 * PITCH + cc * 2;
        const uint32_t sB = sA + A_STAGE_B;

        int s = 0, r = 0;
#pragma unroll 1
        for (int kt = 0; kt < KT; kt++) {
            if (kt >= STAGES)
                mbar_wait(sb + MBAR_EMPTY(s), (r - 1) & 1);
            const uint32_t so = (uint32_t)s * STAGE_B;
            const size_t g = (size_t)kt * BK;
            const __half* a = Ag + g;
            const __half* b = Bg + g;
#pragma unroll 8
            for (int j = 0; j < 32; j++)       // A rows r0 + 4j
                cp_async16(sA + so + j * (4 * PITCH), a + (size_t)j * 4 * K_TOTAL);
#pragma unroll 8
            for (int j = 0; j < 32; j++)       // B rows r0 + 4j
                cp_async16(sB + so + j * (4 * PITCH), b + (size_t)j * 4 * K_TOTAL);
            cp_async_arrive(sb + MBAR_FULL(s));
            if (++s == STAGES) { s = 0; r++; }
        }
        return;
    }

    // ================= consumer warps 0..3 (2x2 grid of 64x64 tiles) ======
    const int wm = (warp >> 1) * 64;   // 0 or 64
    const int wn = (warp & 1) * 64;    // 0 or 64

    float acc[4][8][4];
#pragma unroll
    for (int i = 0; i < 4; i++)
#pragma unroll
        for (int j = 0; j < 8; j++)
#pragma unroll
            for (int r = 0; r < 4; r++) acc[i][j][r] = 0.f;

    // ldmatrix per-lane bases (stage 0)
    const int arow  = lane & 15;
    const int aoff8 = (lane >> 4) * 8;
    const int brow  = (lane & 7) + ((lane >> 4) & 1) * 8;
    const int boff8 = ((lane >> 3) & 1) * 8;
    const uint32_t a_base = sb + (wm + arow) * PITCH + aoff8 * 2;
    const uint32_t b_base = sb + A_STAGE_B + (wn + brow) * PITCH + boff8 * 2;

    int s = 0, ph = 0;
#pragma unroll 1
    for (int kt = 0; kt < KT; kt++) {
        mbar_wait(sb + MBAR_FULL(s), ph);
        const uint32_t boff = (uint32_t)s * STAGE_B;

#pragma unroll
        for (int ks = 0; ks < 4; ks++) {
            uint32_t ar[4][4], br[8][2];
#pragma unroll
            for (int mi = 0; mi < 4; mi++)
                ldsm_x4(ar[mi], a_base + boff + ks * 32 + mi * (16 * PITCH));
#pragma unroll
            for (int nb = 0; nb < 4; nb++) {
                uint32_t r[4];
                ldsm_x4(r, b_base + boff + ks * 32 + nb * (16 * PITCH));
                br[nb * 2][0] = r[0]; br[nb * 2][1] = r[1];
                br[nb * 2 + 1][0] = r[2]; br[nb * 2 + 1][1] = r[3];
            }
            if (ks == 3 && lane == 0)          // all this warp's LDSM for stage done
                mbar_arrive(sb + MBAR_EMPTY(s));
#pragma unroll
            for (int mi = 0; mi < 4; mi++)
#pragma unroll
                for (int ni = 0; ni < 8; ni++)
                    asm volatile(
                        "mma.sync.aligned.m16n8k16.row.col.f32.f16.f16.f32 "
                        "{%0,%1,%2,%3}, {%4,%5,%6,%7}, {%8,%9}, {%0,%1,%2,%3};"
                        : "+f"(acc[mi][ni][0]), "+f"(acc[mi][ni][1]),
                          "+f"(acc[mi][ni][2]), "+f"(acc[mi][ni][3])
                        : "r"(ar[mi][0]), "r"(ar[mi][1]), "r"(ar[mi][2]), "r"(ar[mi][3]),
                          "r"(br[ni][0]), "r"(br[ni][1]));
        }

        if (++s == STAGES) { s = 0; ph ^= 1; }
    }

    // --- epilogue: bias add + fp32 store
#pragma unroll
    for (int mi = 0; mi < 4; mi++) {
        const int row0 = bm + wm + mi * 16 + (lane >> 2);
#pragma unroll
        for (int ni = 0; ni < 8; ni++) {
            const int col = bn + wn + ni * 8 + (lane & 3) * 2;
            const float b0 = bias[col];
            const float b1 = bias[col + 1];
            float2 v0 = make_float2(acc[mi][ni][0] + b0, acc[mi][ni][1] + b1);
            float2 v1 = make_float2(acc[mi][ni][2] + b0, acc[mi][ni][3] + b1);
            *(float2*)&C[(size_t)row0 * N_TOTAL + col]       = v0;
            *(float2*)&C[(size_t)(row0 + 8) * N_TOTAL + col] = v1;
        }
    }
}

// ---------------------------------------------------------------------------
// Launch
// ---------------------------------------------------------------------------
extern "C" void kernel_launch(void* const* d_in, const int* in_sizes, int n_in,
                              void* d_out, int out_size) {
    const float* x     = (const float*)d_in[0];
    const int*   wp    = (const int*)d_in[1];
    const float* scale = (const float*)d_in[2];
    const float* bias  = (const float*)d_in[3];
    float*       out   = (float*)d_out;

    __half* xh = nullptr;
    __half* wh = nullptr;
    cudaGetSymbolAddress((void**)&xh, g_Xh);
    cudaGetSymbolAddress((void**)&wh, g_Wh);

    prep_kernel<<<XB + WB, 256>>>(x, wp, scale, xh, wh);

    cudaFuncSetAttribute(gemm_f16_kernel,
                         cudaFuncAttributeMaxDynamicSharedMemorySize, SMEM_TOTAL);
    dim3 grid(N_TOTAL / BN, M_TOTAL / BM);   // (32, 128)
    gemm_f16_kernel<<<grid, 160, SMEM_TOTAL>>>(xh, wh, bias, out);
}